// round 2
// baseline (speedup 1.0000x reference)
#include <cuda_runtime.h>

#define NN 8192
#define NE 16384
#define W  512
#define NSTRIPS (NE / W)          // 32
#define NPROD 64
#define NCONS 84
#define GRID (NPROD + NCONS)      // 148
#define PROWS (NN / NPROD)        // 128
#define MAXK 13                   // ceil(ceil(8192/84)/8)

// ---- scratch (device globals; no allocation allowed) ----
__device__ float g_u[NN];
__device__ float g_v[NN];
__device__ float g_c[NN];
__device__ float g_ai[NE];
__device__ float g_ao[NE];
__device__ float g_part[2][NPROD][2][W];   // [slot][prod][ai|ao][col]
__device__ int g_doneA[NSTRIPS];
__device__ int g_doneB[NSTRIPS];
__device__ int g_ready[NSTRIPS];
__device__ int g_arr[NSTRIPS + 1];

__device__ __forceinline__ int ld_acq(const int* p) {
    int v;
    asm volatile("ld.acquire.gpu.s32 %0, [%1];" : "=r"(v) : "l"(p) : "memory");
    return v;
}
__device__ __forceinline__ void st_rel(int* p, int v) {
    asm volatile("st.release.gpu.s32 [%0], %1;" :: "l"(p), "r"(v) : "memory");
}
__device__ __forceinline__ void f4add(float4& a, const float4 b) {
    a.x += b.x; a.y += b.y; a.z += b.z; a.w += b.w;
}
__device__ __forceinline__ void f4fma(float4& a, const float4 b, float s) {
    a.x += b.x * s; a.y += b.y * s; a.z += b.z * s; a.w += b.w * s;
}

// K1: per-node scalars u = X·k1, v = X·k2, c = X·k3  +  reset sync flags
__global__ void k1_prep(const float* __restrict__ X, const float* __restrict__ kw) {
    int n = blockIdx.x * blockDim.x + threadIdx.x;
    if (n <= NSTRIPS) {
        if (n < NSTRIPS) { g_doneA[n] = 0; g_doneB[n] = 0; g_ready[n] = 0; }
        g_arr[n] = 0;
    }
    if (n >= NN) return;
    float4 x = reinterpret_cast<const float4*>(X)[n];
    g_u[n] = x.x * kw[0] + x.y * kw[1] + x.z * kw[2]  + x.w * kw[3];
    g_v[n] = x.x * kw[4] + x.y * kw[5] + x.z * kw[6]  + x.w * kw[7];
    g_c[n] = x.x * kw[8] + x.y * kw[9] + x.z * kw[10] + x.w * kw[11];
}

// Fused persistent producer/consumer kernel.
__global__ __launch_bounds__(1024, 1) void fused(const float* __restrict__ Ri,
                                                 const float* __restrict__ Ro,
                                                 const float* __restrict__ ew,
                                                 float* __restrict__ out) {
    __shared__ float4 sbuf[2048];          // 32 KB, multi-purpose
    __shared__ float spu[PROWS], spv[PROWS];
    __shared__ int   sflag;
    __shared__ float sred[8][4];

    const int t   = threadIdx.x;
    const int cta = blockIdx.x;

    if (cta < NPROD) {
        // ======================= PRODUCER =======================
        const int p = cta;
        const int rowbase = p * PROWS;
        if (t < PROWS) { spu[t] = g_u[rowbase + t]; spv[t] = g_v[rowbase + t]; }
        const int col4 = t & 127;      // float4 column group within strip
        const int sub  = t >> 7;       // 0..7 row sub-lane

        for (int s = 0; s <= NSTRIPS; ++s) {
            // --- election: first CTA to arrive at s reduces strip s-1 ---
            if (s >= 1) {
                if (t == 0) sflag = atomicAdd(&g_arr[s], 1);
                __syncthreads();
                if (sflag == 0) {
                    const int q = s - 1, slot = q & 1;
                    if (t == 0) { while (ld_acq(&g_doneA[q]) < NPROD) __nanosleep(32); }
                    __syncthreads();
                    __threadfence();
                    {
                        int out_id = t >> 2;            // 0..255
                        int qq     = t & 3;
                        int which  = out_id >> 7;       // 0: ai, 1: ao
                        int c4     = out_id & 127;
                        float4 sum = make_float4(0.f, 0.f, 0.f, 0.f);
#pragma unroll
                        for (int pp = 0; pp < NPROD / 4; ++pp)
                            f4add(sum, *reinterpret_cast<const float4*>(
                                &g_part[slot][qq * (NPROD / 4) + pp][which][c4 * 4]));
                        sbuf[qq * 256 + out_id] = sum;
                    }
                    __syncthreads();
                    if (t < 256) {
                        int which = t >> 7, c4 = t & 127;
                        float4 r = sbuf[t];
                        f4add(r, sbuf[256 + t]);
                        f4add(r, sbuf[512 + t]);
                        f4add(r, sbuf[768 + t]);
                        float4 wv = *reinterpret_cast<const float4*>(&ew[q * W + c4 * 4]);
                        r.x *= wv.x; r.y *= wv.y; r.z *= wv.z; r.w *= wv.w;
                        if (which == 0)
                            *reinterpret_cast<float4*>(&g_ai[q * W + c4 * 4]) = r;
                        else
                            *reinterpret_cast<float4*>(&g_ao[q * W + c4 * 4]) = r;
                    }
                    __threadfence();
                    __syncthreads();
                    if (t == 0) st_rel(&g_ready[q], 1);
                }
            }
            if (s == NSTRIPS) break;

            // --- flow control: partial-slot reuse + L2 footprint ---
            if (t == 0 && s >= 2) {
                while (ld_acq(&g_ready[s - 2]) == 0) __nanosleep(64);
                while (ld_acq(&g_doneB[s - 2]) < NCONS) __nanosleep(64);
            }
            __syncthreads();

            // --- phase A: column partial reduce over this CTA's 128 rows ---
            const int c0 = s * W + col4 * 4;
            float4 ai = make_float4(0.f, 0.f, 0.f, 0.f);
            float4 ao = make_float4(0.f, 0.f, 0.f, 0.f);
            size_t base = (size_t)(rowbase + sub) * NE + c0;
#pragma unroll 4
            for (int r = 0; r < PROWS / 8; ++r) {
                float4 a = *reinterpret_cast<const float4*>(Ri + base);
                float4 b = *reinterpret_cast<const float4*>(Ro + base);
                float uu = spu[sub + r * 8];
                float vv = spv[sub + r * 8];
                f4fma(ai, b, uu);    // ai += Ro * u
                f4fma(ao, a, vv);    // ao += Ri * v
                base += (size_t)8 * NE;
            }
            // cross-sub tree reduce through smem
            sbuf[sub * 128 + col4]        = ai;
            sbuf[1024 + sub * 128 + col4] = ao;
            __syncthreads();
            if (t < 512) { f4add(sbuf[t], sbuf[t + 512]); f4add(sbuf[1024 + t], sbuf[1536 + t]); }
            __syncthreads();
            if (t < 256) { f4add(sbuf[t], sbuf[t + 256]); f4add(sbuf[1024 + t], sbuf[1280 + t]); }
            __syncthreads();
            if (t < 128) {
                float4 rai = sbuf[t];          f4add(rai, sbuf[t + 128]);
                float4 rao = sbuf[1024 + t];   f4add(rao, sbuf[1152 + t]);
                const int slot = s & 1;
                *reinterpret_cast<float4*>(&g_part[slot][p][0][t * 4]) = rai;
                *reinterpret_cast<float4*>(&g_part[slot][p][1][t * 4]) = rao;
            }
            __threadfence();
            __syncthreads();
            if (t == 0) atomicAdd(&g_doneA[s], 1);
        }
    } else {
        // ======================= CONSUMER =======================
        const int c  = cta - NPROD;
        const int r0 = (int)(((long long)c * NN) / NCONS);
        const int r1 = (int)(((long long)(c + 1) * NN) / NCONS);
        const int team = t >> 7;       // 0..7 (row team)
        const int lane = t & 127;      // float4 col group
        const int warp = (t >> 5) & 3; // warp within team
        const int l32  = t & 31;

        float acc[MAXK];
#pragma unroll
        for (int k = 0; k < MAXK; ++k) acc[k] = 0.f;

        float4* s_ai = sbuf;        // 128 float4
        float4* s_ao = sbuf + 128;  // 128 float4

        for (int s = 0; s < NSTRIPS; ++s) {
            if (t == 0) { while (ld_acq(&g_ready[s]) == 0) __nanosleep(64); }
            __syncthreads();
            if (t < 128)
                s_ai[t] = *reinterpret_cast<const float4*>(&g_ai[s * W + t * 4]);
            else if (t < 256)
                s_ao[t - 128] = *reinterpret_cast<const float4*>(&g_ao[s * W + (t - 128) * 4]);
            __syncthreads();

            const float4 vai = s_ai[lane];
            const float4 vao = s_ao[lane];
            const size_t cbase = (size_t)s * W + lane * 4;
#pragma unroll
            for (int k = 0; k < MAXK; ++k) {
                int row = r0 + team + k * 8;
                if (row < r1) {
                    const float4 a = *reinterpret_cast<const float4*>(Ri + (size_t)row * NE + cbase);
                    const float4 b = *reinterpret_cast<const float4*>(Ro + (size_t)row * NE + cbase);
                    acc[k] += a.x * vai.x + a.y * vai.y + a.z * vai.z + a.w * vai.w
                            + b.x * vao.x + b.y * vao.y + b.z * vao.z + b.w * vao.w;
                }
            }
            __syncthreads();
            if (t == 0) atomicAdd(&g_doneB[s], 1);
        }

        // final per-row reduction (128 threads -> 1 scalar per row)
#pragma unroll
        for (int k = 0; k < MAXK; ++k) {
            int row = r0 + team + k * 8;
            float vsum = acc[k];
#pragma unroll
            for (int off = 16; off; off >>= 1)
                vsum += __shfl_down_sync(0xffffffffu, vsum, off);
            if (l32 == 0) sred[team][warp] = vsum;
            __syncthreads();
            if (lane == 0 && row < r1)
                out[row] = sred[team][0] + sred[team][1] + sred[team][2] + sred[team][3]
                         + g_c[row];
            __syncthreads();
        }
    }
}

extern "C" void kernel_launch(void* const* d_in, const int* in_sizes, int n_in,
                              void* d_out, int out_size) {
    const float* X    = (const float*)d_in[0];  // [N,4]
    const float* ew   = (const float*)d_in[1];  // [E,1]
    const float* Ri   = (const float*)d_in[2];  // [N,E]
    const float* Ro   = (const float*)d_in[3];  // [N,E]
    const float* kern = (const float*)d_in[4];  // [12,1]
    float* out = (float*)d_out;                 // [N,1]

    k1_prep<<<NN / 256, 256>>>(X, kern);
    fused<<<GRID, 1024>>>(Ri, Ro, ew, out);
}